// round 14
// baseline (speedup 1.0000x reference)
#include <cuda_runtime.h>
#include <cuda_fp16.h>
#include <cstdint>

#define NB 8
#define LQ 256
#define LK 256
#define HH 256
#define DV 256

// Scratch (allocation-free rule: device globals)
__device__ float g_Qp[NB * LQ * HH];
__device__ float g_Kp[NB * LK * HH];
__device__ float g_S[NB * LQ * LK];       // exp(scores), unnormalized
__device__ float g_colsum[NB * LK];       // per-column sums of exp

__device__ __forceinline__ uint32_t f2tf(float x) {
    uint32_t r;
    asm("cvt.rna.tf32.f32 %0, %1;" : "=r"(r) : "f"(x));
    return r;
}

__device__ __forceinline__ uint32_t h2u(__half2 h) { return *(uint32_t*)&h; }

__device__ __forceinline__ uint32_t tanh2u(uint32_t x) {
    uint32_t y;
    asm("tanh.approx.f16x2 %0, %1;" : "=r"(y) : "r"(x));
    return y;
}

__device__ __forceinline__ uint32_t hadd2u(uint32_t a, uint32_t b) {
    uint32_t r;
    asm("add.rn.f16x2 %0, %1, %2;" : "=r"(r) : "r"(a), "r"(b));
    return r;
}

// D += A(16x8,row) * B(8x8,col)  in tf32, fp32 accum
__device__ __forceinline__ void mma8(float* d, const uint32_t* a, const uint32_t* b) {
    asm("mma.sync.aligned.m16n8k8.row.col.f32.tf32.tf32.f32 "
        "{%0,%1,%2,%3}, {%4,%5,%6,%7}, {%8,%9}, {%0,%1,%2,%3};"
        : "+f"(d[0]), "+f"(d[1]), "+f"(d[2]), "+f"(d[3])
        : "r"(a[0]), "r"(a[1]), "r"(a[2]), "r"(a[3]), "r"(b[0]), "r"(b[1]));
}

// D += A(16x16 f16,row) * B(16x8 f16,col), fp32 accum
__device__ __forceinline__ void mma16816(float* d, uint32_t a0, uint32_t a1,
                                         uint32_t a2, uint32_t a3,
                                         uint32_t b0, uint32_t b1) {
    asm("mma.sync.aligned.m16n8k16.row.col.f32.f16.f16.f32 "
        "{%0,%1,%2,%3}, {%4,%5,%6,%7}, {%8,%9}, {%0,%1,%2,%3};"
        : "+f"(d[0]), "+f"(d[1]), "+f"(d[2]), "+f"(d[3])
        : "r"(a0), "r"(a1), "r"(a2), "r"(a3), "r"(b0), "r"(b1));
}

#define TS 36  // smem stride, k-contiguous tf32 tiles (fragment LDS conflict-free)
#define VS 35  // smem stride, transposed V tile (<=2-way)
#define SQ 132 // scores smem stride in half2 units: 132%32==4 -> conflict-free frags

// ---------------------------------------------------------------------------
// proj_kernel, grid (4, 32, 3):
//   z=0: g_Qp = queries @ W_q^T   (tf32 NT GEMM, 64x64 tiles — R5/R9 structure)
//   z=1: g_Kp = keyes   @ W_k^T
//   z=2: zero g_colsum (only 16 blocks do work)
// ---------------------------------------------------------------------------
__global__ void __launch_bounds__(128) proj_kernel(
    const float* __restrict__ Xq, const float* __restrict__ Wq,
    const float* __restrict__ Xk, const float* __restrict__ Wk) {
    const int tid = threadIdx.x;

    if (blockIdx.z == 2) {
        if (blockIdx.x == 0 && blockIdx.y < 16)
            g_colsum[blockIdx.y * 128 + tid] = 0.f;
        return;
    }

    const float* X;
    const float* W;
    float* C;
    if (blockIdx.z == 0) { X = Xq; W = Wq; C = g_Qp; }
    else                 { X = Xk; W = Wk; C = g_Kp; }

    __shared__ uint32_t Xs[2][64 * TS];
    __shared__ uint32_t Ws[2][64 * TS];

    const int lane = tid & 31;
    const int warp = tid >> 5;
    const int gid = lane >> 2;
    const int tig = lane & 3;
    const int wm = (warp & 1) * 32;
    const int wn = (warp >> 1) * 32;
    const int m0 = blockIdx.y * 64;
    const int n0 = blockIdx.x * 64;

    int srow[4], sc4[4];
    #pragma unroll
    for (int j = 0; j < 4; j++) {
        int idx = tid + j * 128;
        srow[j] = idx >> 3;
        sc4[j]  = idx & 7;
    }

    float d[2][4][4];
    #pragma unroll
    for (int i = 0; i < 2; i++)
        #pragma unroll
        for (int j = 0; j < 4; j++)
            #pragma unroll
            for (int e = 0; e < 4; e++) d[i][j][e] = 0.f;

    float4 xv[4], wv[4];
    #pragma unroll
    for (int j = 0; j < 4; j++) {
        xv[j] = *(const float4*)&X[(m0 + srow[j]) * 256 + sc4[j] * 4];
        wv[j] = *(const float4*)&W[(n0 + srow[j]) * 256 + sc4[j] * 4];
    }

    for (int c = 0; c < 8; c++) {
        uint32_t* XB = Xs[c & 1];
        uint32_t* WB = Ws[c & 1];
        #pragma unroll
        for (int j = 0; j < 4; j++) {
            uint32_t* px = &XB[srow[j] * TS + sc4[j] * 4];
            px[0] = f2tf(xv[j].x); px[1] = f2tf(xv[j].y);
            px[2] = f2tf(xv[j].z); px[3] = f2tf(xv[j].w);
            uint32_t* pw = &WB[srow[j] * TS + sc4[j] * 4];
            pw[0] = f2tf(wv[j].x); pw[1] = f2tf(wv[j].y);
            pw[2] = f2tf(wv[j].z); pw[3] = f2tf(wv[j].w);
        }
        __syncthreads();

        if (c < 7) {
            const int k0 = (c + 1) * 32;
            #pragma unroll
            for (int j = 0; j < 4; j++) {
                xv[j] = *(const float4*)&X[(m0 + srow[j]) * 256 + k0 + sc4[j] * 4];
                wv[j] = *(const float4*)&W[(n0 + srow[j]) * 256 + k0 + sc4[j] * 4];
            }
        }

        #pragma unroll
        for (int ks = 0; ks < 4; ks++) {
            const int kk = ks * 8;
            uint32_t a[2][4], b[4][2];
            #pragma unroll
            for (int i = 0; i < 2; i++) {
                int r = wm + i * 16 + gid;
                a[i][0] = XB[r * TS + kk + tig];
                a[i][1] = XB[(r + 8) * TS + kk + tig];
                a[i][2] = XB[r * TS + kk + tig + 4];
                a[i][3] = XB[(r + 8) * TS + kk + tig + 4];
            }
            #pragma unroll
            for (int jn = 0; jn < 4; jn++) {
                int n = wn + jn * 8 + gid;
                b[jn][0] = WB[n * TS + kk + tig];
                b[jn][1] = WB[n * TS + kk + tig + 4];
            }
            #pragma unroll
            for (int i = 0; i < 2; i++)
                #pragma unroll
                for (int jn = 0; jn < 4; jn++) mma8(d[i][jn], a[i], b[jn]);
        }
    }

    #pragma unroll
    for (int i = 0; i < 2; i++)
        #pragma unroll
        for (int jn = 0; jn < 4; jn++) {
            int row = m0 + wm + i * 16 + gid;
            int col = n0 + wn + jn * 8 + tig * 2;
            *(float2*)&C[row * 256 + col] = make_float2(d[i][jn][0], d[i][jn][1]);
            *(float2*)&C[(row + 8) * 256 + col] = make_float2(d[i][jn][2], d[i][jn][3]);
        }
}

// ---------------------------------------------------------------------------
// Scores (HMMA accumulation) + FUSED exp + column sums:
//   g_S[q][k]     = exp(sum_h Wv[h]*tanh(Qp[q][h]+Kp[k][h]))   (1.0 if k>=vl)
//   g_colsum[b,k] += partial column sums (atomics)
// No max-subtraction needed: |score| <= sum|Wv| ~ 8, exp is overflow-safe.
// Masked column -> all 1.0 -> softmax = 1/256 (matches reference exactly).
// Block: 32q x 32k tile, 8 warps, grid (8,8,8).
// ---------------------------------------------------------------------------
__global__ void __launch_bounds__(256) scores_kernel(
    const float* __restrict__ Wv, const int* __restrict__ vlens) {
    const int b = blockIdx.z;
    const int q0 = blockIdx.y * 32;
    const int k0 = blockIdx.x * 32;
    const int tid = threadIdx.x;
    const int vl = vlens[b];
    float* S = g_S + b * LQ * LK;

    if (k0 >= vl) {
        // whole tile masked: exp(const)=1 everywhere
        const int qr = tid >> 3;
        const int k4 = tid & 7;
        const float4 ones = make_float4(1.f, 1.f, 1.f, 1.f);
        *(float4*)&S[(q0 + qr) * LK + k0 + k4 * 4] = ones;
        if (tid < 32) atomicAdd(&g_colsum[b * LK + k0 + tid], 32.0f);
        return;
    }

    __shared__ uint32_t Qs[32 * SQ];   // [q][hp] half2, full K=256 h
    __shared__ uint32_t Ks[32 * SQ];   // [k][hp] half2
    __shared__ uint32_t Wv2s[128];     // Wv as half2 pairs
    __shared__ float csum[32];         // block-local column sums

    if (tid < 128) {
        float2 wv = *(const float2*)&Wv[tid * 2];
        Wv2s[tid] = h2u(__floats2half2_rn(wv.x, wv.y));
    }
    if (tid < 32) csum[tid] = 0.f;

    // stage Q and K tiles (fp32 -> half2), coalesced float4 loads
    {
        const float* Qb = g_Qp + (b * LQ + q0) * HH;
        const float* Kb = g_Kp + (b * LK + k0) * HH;
        const int row = tid >> 3;
        const int c8 = tid & 7;
        #pragma unroll
        for (int j = 0; j < 8; j++) {
            const int c4 = j * 8 + c8;
            float4 qv = *(const float4*)&Qb[row * HH + c4 * 4];
            uint2 qp = make_uint2(h2u(__floats2half2_rn(qv.x, qv.y)),
                                  h2u(__floats2half2_rn(qv.z, qv.w)));
            *(uint2*)&Qs[row * SQ + c4 * 2] = qp;
            float4 kv = *(const float4*)&Kb[row * HH + c4 * 4];
            uint2 kp = make_uint2(h2u(__floats2half2_rn(kv.x, kv.y)),
                                  h2u(__floats2half2_rn(kv.z, kv.w)));
            *(uint2*)&Ks[row * SQ + c4 * 2] = kp;
        }
    }
    __syncthreads();

    const int lane = tid & 31;
    const int warp = tid >> 5;
    const int gid = lane >> 2;
    const int tig = lane & 3;

    const uint32_t* Qp0 = &Qs[(warp * 4) * SQ];

    float d[8][4];
    #pragma unroll
    for (int i = 0; i < 8; i++)
        #pragma unroll
        for (int e = 0; e < 4; e++) d[i][e] = 0.f;

    #pragma unroll 4
    for (int c = 0; c < 16; c++) {
        const int hp0 = c * 8 + tig;
        const int hp1 = hp0 + 4;
        const uint32_t rb0 = Wv2s[hp0];
        const uint32_t rb1 = Wv2s[hp1];
        uint32_t kf[2][4];
        #pragma unroll
        for (int kh = 0; kh < 2; kh++) {
            const uint32_t* Kb0 = &Ks[(kh * 16 + gid) * SQ];
            kf[kh][0] = Kb0[hp0];
            kf[kh][1] = Kb0[hp1];
            kf[kh][2] = Kb0[8 * SQ + hp0];
            kf[kh][3] = Kb0[8 * SQ + hp1];
        }
        #pragma unroll
        for (int q = 0; q < 4; q++) {
            const uint32_t qv0 = Qp0[q * SQ + hp0];
            const uint32_t qv1 = Qp0[q * SQ + hp1];
            #pragma unroll
            for (int kh = 0; kh < 2; kh++) {
                uint32_t a0 = tanh2u(hadd2u(qv0, kf[kh][0]));
                uint32_t a1 = tanh2u(hadd2u(qv0, kf[kh][2]));
                uint32_t a2 = tanh2u(hadd2u(qv1, kf[kh][1]));
                uint32_t a3 = tanh2u(hadd2u(qv1, kf[kh][3]));
                mma16816(d[q * 2 + kh], a0, a1, a2, a3, rb0, rb1);
            }
        }
    }

    // Epilogue: exp, write, accumulate column sums
    #pragma unroll
    for (int s = 0; s < 2; s++) {
        const int rg = tig + s * 4;
        const int qq = rg >> 1;
        const int kh = rg & 1;
        const int qrow = q0 + warp * 4 + qq;
        const int k1 = k0 + kh * 16 + gid;
        const int k2 = k1 + 8;
        float e1 = (k1 < vl) ? __expf(d[rg][0]) : 1.0f;
        float e2 = (k2 < vl) ? __expf(d[rg][2]) : 1.0f;
        S[qrow * LK + k1] = e1;
        S[qrow * LK + k2] = e2;
        atomicAdd(&csum[k1 - k0], e1);
        atomicAdd(&csum[k2 - k0], e2);
    }
    __syncthreads();
    if (tid < 32) atomicAdd(&g_colsum[b * LK + k0 + tid], csum[tid]);
}

// ---------------------------------------------------------------------------
// Output NN GEMM (tf32): out[b][q][d] = sum_k (E[q][k]/colsum[k]) * V[k][d]
// Normalization folded into V staging (V row k scaled by 1/colsum[k]).
// CTA 32q x 32d, 4 warps (2x2), warp tile 16x16; V staged transposed [d][k].
// grid (8, 8, 8) = 512 blocks.
// ---------------------------------------------------------------------------
__global__ void __launch_bounds__(128) out_kernel(
    const float* __restrict__ Vv, float* __restrict__ out) {
    const int b = blockIdx.z;
    const int q0 = blockIdx.y * 32;
    const int d0 = blockIdx.x * 32;
    const int tid = threadIdx.x;
    const int lane = tid & 31;
    const int warp = tid >> 5;
    const int gid = lane >> 2;
    const int tig = lane & 3;
    const int wq = (warp & 1) * 16;
    const int wn = (warp >> 1) * 16;

    const float* A = g_S + b * LQ * LK;
    const float* V = Vv + b * LK * DV;
    const float* CS = g_colsum + b * LK;

    __shared__ uint32_t As[2][32 * TS];
    __shared__ uint32_t Vs[2][32 * VS];

    int srow[2], sc4[2];
    #pragma unroll
    for (int j = 0; j < 2; j++) {
        int idx = tid + j * 128;
        srow[j] = idx >> 3;
        sc4[j]  = idx & 7;
    }

    float d[2][4] = {};

    float4 av[2], vv[2];
    float inv[2];
    #pragma unroll
    for (int j = 0; j < 2; j++) {
        av[j] = *(const float4*)&A[(q0 + srow[j]) * LK + sc4[j] * 4];
        vv[j] = *(const float4*)&V[srow[j] * DV + d0 + sc4[j] * 4];
        inv[j] = __fdividef(1.0f, CS[srow[j]]);
    }

    for (int c = 0; c < 8; c++) {
        uint32_t* AB = As[c & 1];
        uint32_t* VB = Vs[c & 1];
        #pragma unroll
        for (int j = 0; j < 2; j++) {
            uint32_t* pa = &AB[srow[j] * TS + sc4[j] * 4];
            pa[0] = f2tf(av[j].x); pa[1] = f2tf(av[j].y);
            pa[2] = f2tf(av[j].z); pa[3] = f2tf(av[j].w);
            const int dc = sc4[j] * 4;
            const float iv = inv[j];
            VB[(dc + 0) * VS + srow[j]] = f2tf(vv[j].x * iv);
            VB[(dc + 1) * VS + srow[j]] = f2tf(vv[j].y * iv);
            VB[(dc + 2) * VS + srow[j]] = f2tf(vv[j].z * iv);
            VB[(dc + 3) * VS + srow[j]] = f2tf(vv[j].w * iv);
        }
        __syncthreads();

        if (c < 7) {
            const int k0 = (c + 1) * 32;
            #pragma unroll
            for (int j = 0; j < 2; j++) {
                av[j] = *(const float4*)&A[(q0 + srow[j]) * LK + k0 + sc4[j] * 4];
                vv[j] = *(const float4*)&V[(k0 + srow[j]) * DV + d0 + sc4[j] * 4];
                inv[j] = __fdividef(1.0f, CS[k0 + srow[j]]);
            }
        }

        #pragma unroll
        for (int ks = 0; ks < 4; ks++) {
            const int kk = ks * 8;
            uint32_t a[4], bfr[2][2];
            const int r = wq + gid;
            a[0] = AB[r * TS + kk + tig];
            a[1] = AB[(r + 8) * TS + kk + tig];
            a[2] = AB[r * TS + kk + tig + 4];
            a[3] = AB[(r + 8) * TS + kk + tig + 4];
            #pragma unroll
            for (int jn = 0; jn < 2; jn++) {
                int n = wn + jn * 8 + gid;
                bfr[jn][0] = VB[n * VS + kk + tig];
                bfr[jn][1] = VB[n * VS + kk + tig + 4];
            }
            mma8(d[0], a, bfr[0]);
            mma8(d[1], a, bfr[1]);
        }
    }

    float* O = out + b * LQ * DV;
    #pragma unroll
    for (int jn = 0; jn < 2; jn++) {
        int row = q0 + wq + gid;
        int col = d0 + wn + jn * 8 + tig * 2;
        *(float2*)&O[row * DV + col] = make_float2(d[jn][0], d[jn][1]);
        *(float2*)&O[(row + 8) * DV + col] = make_float2(d[jn][2], d[jn][3]);
    }
}

extern "C" void kernel_launch(void* const* d_in, const int* in_sizes, int n_in,
                              void* d_out, int out_size) {
    const float* queries    = (const float*)d_in[0];
    const float* keyes      = (const float*)d_in[1];
    const float* values     = (const float*)d_in[2];
    const int*   valid_lens = (const int*)d_in[3];
    const float* W_q        = (const float*)d_in[4];
    const float* W_k        = (const float*)d_in[5];
    const float* W_v        = (const float*)d_in[6];
    float* out = (float*)d_out;

    proj_kernel<<<dim3(4, 32, 3), 128>>>(queries, W_q, keyes, W_k);
    scores_kernel<<<dim3(8, 8, 8), 256>>>(W_v, valid_lens);
    out_kernel<<<dim3(8, 8, 8), 128>>>(values, out);
}

// round 15
// speedup vs baseline: 1.2556x; 1.2556x over previous
#include <cuda_runtime.h>
#include <cuda_fp16.h>
#include <cstdint>

#define NB 8
#define LQ 256
#define LK 256
#define HH 256
#define DV 256

// Scratch (allocation-free rule: device globals)
__device__ float g_Qp[NB * LQ * HH];
__device__ float g_Kp[NB * LK * HH];
__device__ float g_S[NB * LQ * LK];       // exp(scores), unnormalized
__device__ float g_colsum[NB * LK];       // per-column sums of exp

__device__ __forceinline__ uint32_t f2tf(float x) {
    uint32_t r;
    asm("cvt.rna.tf32.f32 %0, %1;" : "=r"(r) : "f"(x));
    return r;
}

__device__ __forceinline__ uint32_t h2u(__half2 h) { return *(uint32_t*)&h; }

__device__ __forceinline__ uint32_t tanh2u(uint32_t x) {
    uint32_t y;
    asm("tanh.approx.f16x2 %0, %1;" : "=r"(y) : "r"(x));
    return y;
}

__device__ __forceinline__ uint32_t hadd2u(uint32_t a, uint32_t b) {
    uint32_t r;
    asm("add.rn.f16x2 %0, %1, %2;" : "=r"(r) : "r"(a), "r"(b));
    return r;
}

// D += A(16x8,row) * B(8x8,col)  in tf32, fp32 accum
__device__ __forceinline__ void mma8(float* d, const uint32_t* a, const uint32_t* b) {
    asm("mma.sync.aligned.m16n8k8.row.col.f32.tf32.tf32.f32 "
        "{%0,%1,%2,%3}, {%4,%5,%6,%7}, {%8,%9}, {%0,%1,%2,%3};"
        : "+f"(d[0]), "+f"(d[1]), "+f"(d[2]), "+f"(d[3])
        : "r"(a[0]), "r"(a[1]), "r"(a[2]), "r"(a[3]), "r"(b[0]), "r"(b[1]));
}

// D += A(16x16 f16,row) * B(16x8 f16,col), fp32 accum
__device__ __forceinline__ void mma16816(float* d, uint32_t a0, uint32_t a1,
                                         uint32_t a2, uint32_t a3,
                                         uint32_t b0, uint32_t b1) {
    asm("mma.sync.aligned.m16n8k16.row.col.f32.f16.f16.f32 "
        "{%0,%1,%2,%3}, {%4,%5,%6,%7}, {%8,%9}, {%0,%1,%2,%3};"
        : "+f"(d[0]), "+f"(d[1]), "+f"(d[2]), "+f"(d[3])
        : "r"(a0), "r"(a1), "r"(a2), "r"(a3), "r"(b0), "r"(b1));
}

#define TS 36  // smem stride, k-contiguous tf32 tiles (fragment LDS conflict-free)
#define VS 35  // smem stride, transposed V tile (<=2-way)
#define SQ 132 // scores smem stride in half2 units: 132%32==4 -> conflict-free frags

// ---------------------------------------------------------------------------
// proj_kernel, grid (4, 32, 3):
//   z=0: g_Qp = queries @ W_q^T   (tf32 NT GEMM, 64x64 tiles)
//   z=1: g_Kp = keyes   @ W_k^T
//   z=2: zero g_colsum (only 16 blocks do work)
// ---------------------------------------------------------------------------
__global__ void __launch_bounds__(128) proj_kernel(
    const float* __restrict__ Xq, const float* __restrict__ Wq,
    const float* __restrict__ Xk, const float* __restrict__ Wk) {
    const int tid = threadIdx.x;

    if (blockIdx.z == 2) {
        if (blockIdx.x == 0 && blockIdx.y < 16)
            g_colsum[blockIdx.y * 128 + tid] = 0.f;
        return;
    }

    const float* X;
    const float* W;
    float* C;
    if (blockIdx.z == 0) { X = Xq; W = Wq; C = g_Qp; }
    else                 { X = Xk; W = Wk; C = g_Kp; }

    __shared__ uint32_t Xs[2][64 * TS];
    __shared__ uint32_t Ws[2][64 * TS];

    const int lane = tid & 31;
    const int warp = tid >> 5;
    const int gid = lane >> 2;
    const int tig = lane & 3;
    const int wm = (warp & 1) * 32;
    const int wn = (warp >> 1) * 32;
    const int m0 = blockIdx.y * 64;
    const int n0 = blockIdx.x * 64;

    int srow[4], sc4[4];
    #pragma unroll
    for (int j = 0; j < 4; j++) {
        int idx = tid + j * 128;
        srow[j] = idx >> 3;
        sc4[j]  = idx & 7;
    }

    float d[2][4][4];
    #pragma unroll
    for (int i = 0; i < 2; i++)
        #pragma unroll
        for (int j = 0; j < 4; j++)
            #pragma unroll
            for (int e = 0; e < 4; e++) d[i][j][e] = 0.f;

    float4 xv[4], wv[4];
    #pragma unroll
    for (int j = 0; j < 4; j++) {
        xv[j] = *(const float4*)&X[(m0 + srow[j]) * 256 + sc4[j] * 4];
        wv[j] = *(const float4*)&W[(n0 + srow[j]) * 256 + sc4[j] * 4];
    }

    for (int c = 0; c < 8; c++) {
        uint32_t* XB = Xs[c & 1];
        uint32_t* WB = Ws[c & 1];
        #pragma unroll
        for (int j = 0; j < 4; j++) {
            uint32_t* px = &XB[srow[j] * TS + sc4[j] * 4];
            px[0] = f2tf(xv[j].x); px[1] = f2tf(xv[j].y);
            px[2] = f2tf(xv[j].z); px[3] = f2tf(xv[j].w);
            uint32_t* pw = &WB[srow[j] * TS + sc4[j] * 4];
            pw[0] = f2tf(wv[j].x); pw[1] = f2tf(wv[j].y);
            pw[2] = f2tf(wv[j].z); pw[3] = f2tf(wv[j].w);
        }
        __syncthreads();

        if (c < 7) {
            const int k0 = (c + 1) * 32;
            #pragma unroll
            for (int j = 0; j < 4; j++) {
                xv[j] = *(const float4*)&X[(m0 + srow[j]) * 256 + k0 + sc4[j] * 4];
                wv[j] = *(const float4*)&W[(n0 + srow[j]) * 256 + k0 + sc4[j] * 4];
            }
        }

        #pragma unroll
        for (int ks = 0; ks < 4; ks++) {
            const int kk = ks * 8;
            uint32_t a[2][4], b[4][2];
            #pragma unroll
            for (int i = 0; i < 2; i++) {
                int r = wm + i * 16 + gid;
                a[i][0] = XB[r * TS + kk + tig];
                a[i][1] = XB[(r + 8) * TS + kk + tig];
                a[i][2] = XB[r * TS + kk + tig + 4];
                a[i][3] = XB[(r + 8) * TS + kk + tig + 4];
            }
            #pragma unroll
            for (int jn = 0; jn < 4; jn++) {
                int n = wn + jn * 8 + gid;
                b[jn][0] = WB[n * TS + kk + tig];
                b[jn][1] = WB[n * TS + kk + tig + 4];
            }
            #pragma unroll
            for (int i = 0; i < 2; i++)
                #pragma unroll
                for (int jn = 0; jn < 4; jn++) mma8(d[i][jn], a[i], b[jn]);
        }
    }

    #pragma unroll
    for (int i = 0; i < 2; i++)
        #pragma unroll
        for (int jn = 0; jn < 4; jn++) {
            int row = m0 + wm + i * 16 + gid;
            int col = n0 + wn + jn * 8 + tig * 2;
            *(float2*)&C[row * 256 + col] = make_float2(d[i][jn][0], d[i][jn][1]);
            *(float2*)&C[(row + 8) * 256 + col] = make_float2(d[i][jn][2], d[i][jn][3]);
        }
}

// ---------------------------------------------------------------------------
// Scores (HMMA accumulation) + fused exp + column sums — FINE-GRAINED tiles:
//   16q x 32k per block, 256 threads (8 warps x 2 q-rows), grid (8,16,8).
// Halved per-block work -> ~3.7 fine waves of active blocks instead of 2
// ragged ones -> less wave-quantization above the MUFU floor.
//   g_S[q][k]     = exp(sum_h Wv[h]*tanh(Qp[q][h]+Kp[k][h]))  (1.0 if k>=vl)
//   g_colsum[b,k] += column sums (atomics)
// ---------------------------------------------------------------------------
__global__ void __launch_bounds__(256) scores_kernel(
    const float* __restrict__ Wv, const int* __restrict__ vlens) {
    const int b = blockIdx.z;
    const int q0 = blockIdx.y * 16;
    const int k0 = blockIdx.x * 32;
    const int tid = threadIdx.x;
    const int vl = vlens[b];
    float* S = g_S + b * LQ * LK;

    if (k0 >= vl) {
        // whole tile masked: exp(const)=1 everywhere (16x32 = 512 floats)
        const int qr = tid >> 4;          // 0..15
        const int kp = tid & 15;          // 0..15
        *(float2*)&S[(q0 + qr) * LK + k0 + kp * 2] = make_float2(1.f, 1.f);
        if (tid < 32) atomicAdd(&g_colsum[b * LK + k0 + tid], 16.0f);
        return;
    }

    __shared__ uint32_t Qs[16 * SQ];   // [q][hp] half2, full 256 h
    __shared__ uint32_t Ks[32 * SQ];   // [k][hp] half2
    __shared__ uint32_t Wv2s[128];     // Wv as half2 pairs
    __shared__ float csum[32];

    if (tid < 128) {
        float2 wv = *(const float2*)&Wv[tid * 2];
        Wv2s[tid] = h2u(__floats2half2_rn(wv.x, wv.y));
    }
    if (tid < 32) csum[tid] = 0.f;

    // stage Q (16 rows, 4 float4/thread) and K (32 rows, 8 float4/thread)
    {
        const float* Qb = g_Qp + (b * LQ + q0) * HH;
        const int qrow = tid >> 4;        // 0..15
        const int qc = tid & 15;          // 0..15
        #pragma unroll
        for (int j = 0; j < 4; j++) {
            const int c4 = j * 16 + qc;   // float4 index 0..63
            float4 qv = *(const float4*)&Qb[qrow * HH + c4 * 4];
            uint2 qp = make_uint2(h2u(__floats2half2_rn(qv.x, qv.y)),
                                  h2u(__floats2half2_rn(qv.z, qv.w)));
            *(uint2*)&Qs[qrow * SQ + c4 * 2] = qp;
        }
        const float* Kb = g_Kp + (b * LK + k0) * HH;
        const int krow = tid >> 3;        // 0..31
        const int kc = tid & 7;           // 0..7
        #pragma unroll
        for (int j = 0; j < 8; j++) {
            const int c4 = j * 8 + kc;
            float4 kv = *(const float4*)&Kb[krow * HH + c4 * 4];
            uint2 kp = make_uint2(h2u(__floats2half2_rn(kv.x, kv.y)),
                                  h2u(__floats2half2_rn(kv.z, kv.w)));
            *(uint2*)&Ks[krow * SQ + c4 * 2] = kp;
        }
    }
    __syncthreads();

    const int lane = tid & 31;
    const int warp = tid >> 5;           // 0..7 -> q rows warp*2, warp*2+1
    const int gid = lane >> 2;
    const int tig = lane & 3;

    const uint32_t* Qp0 = &Qs[(warp * 2) * SQ];

    float d[4][4];   // d[q*2+kh]
    #pragma unroll
    for (int i = 0; i < 4; i++)
        #pragma unroll
        for (int e = 0; e < 4; e++) d[i][e] = 0.f;

    #pragma unroll 4
    for (int c = 0; c < 16; c++) {
        const int hp0 = c * 8 + tig;
        const int hp1 = hp0 + 4;
        const uint32_t rb0 = Wv2s[hp0];
        const uint32_t rb1 = Wv2s[hp1];
        uint32_t kf[2][4];
        #pragma unroll
        for (int kh = 0; kh < 2; kh++) {
            const uint32_t* Kb0 = &Ks[(kh * 16 + gid) * SQ];
            kf[kh][0] = Kb0[hp0];
            kf[kh][1] = Kb0[hp1];
            kf[kh][2] = Kb0[8 * SQ + hp0];
            kf[kh][3] = Kb0[8 * SQ + hp1];
        }
        #pragma unroll
        for (int q = 0; q < 2; q++) {
            const uint32_t qv0 = Qp0[q * SQ + hp0];
            const uint32_t qv1 = Qp0[q * SQ + hp1];
            #pragma unroll
            for (int kh = 0; kh < 2; kh++) {
                uint32_t a0 = tanh2u(hadd2u(qv0, kf[kh][0]));
                uint32_t a1 = tanh2u(hadd2u(qv0, kf[kh][2]));
                uint32_t a2 = tanh2u(hadd2u(qv1, kf[kh][1]));
                uint32_t a3 = tanh2u(hadd2u(qv1, kf[kh][3]));
                mma16816(d[q * 2 + kh], a0, a1, a2, a3, rb0, rb1);
            }
        }
    }

    // Epilogue: each lane writes the accumulator indexed by its tig
    {
        const int rg = tig;               // 0..3
        const int qq = rg >> 1;
        const int kh = rg & 1;
        const int qrow = q0 + warp * 2 + qq;
        const int k1 = k0 + kh * 16 + gid;
        const int k2 = k1 + 8;
        float e1 = (k1 < vl) ? __expf(d[rg][0]) : 1.0f;
        float e2 = (k2 < vl) ? __expf(d[rg][2]) : 1.0f;
        S[qrow * LK + k1] = e1;
        S[qrow * LK + k2] = e2;
        atomicAdd(&csum[k1 - k0], e1);
        atomicAdd(&csum[k2 - k0], e2);
    }
    __syncthreads();
    if (tid < 32) atomicAdd(&g_colsum[b * LK + k0 + tid], csum[tid]);
}

// ---------------------------------------------------------------------------
// Output NN GEMM (tf32): out[b][q][d] = sum_k (E[q][k]/colsum[k]) * V[k][d]
// Normalization folded into V staging. CTA 32q x 32d, 4 warps, grid (8,8,8).
// ---------------------------------------------------------------------------
__global__ void __launch_bounds__(128) out_kernel(
    const float* __restrict__ Vv, float* __restrict__ out) {
    const int b = blockIdx.z;
    const int q0 = blockIdx.y * 32;
    const int d0 = blockIdx.x * 32;
    const int tid = threadIdx.x;
    const int lane = tid & 31;
    const int warp = tid >> 5;
    const int gid = lane >> 2;
    const int tig = lane & 3;
    const int wq = (warp & 1) * 16;
    const int wn = (warp >> 1) * 16;

    const float* A = g_S + b * LQ * LK;
    const float* V = Vv + b * LK * DV;
    const float* CS = g_colsum + b * LK;

    __shared__ uint32_t As[2][32 * TS];
    __shared__ uint32_t Vs[2][32 * VS];

    int srow[2], sc4[2];
    #pragma unroll
    for (int j = 0; j < 2; j++) {
        int idx = tid + j * 128;
        srow[j] = idx >> 3;
        sc4[j]  = idx & 7;
    }

    float d[2][4] = {};

    float4 av[2], vv[2];
    float inv[2];
    #pragma unroll
    for (int j = 0; j < 2; j++) {
        av[j] = *(const float4*)&A[(q0 + srow[j]) * LK + sc4[j] * 4];
        vv[j] = *(const float4*)&V[srow[j] * DV + d0 + sc4[j] * 4];
        inv[j] = __fdividef(1.0f, CS[srow[j]]);
    }

    for (int c = 0; c < 8; c++) {
        uint32_t* AB = As[c & 1];
        uint32_t* VB = Vs[c & 1];
        #pragma unroll
        for (int j = 0; j < 2; j++) {
            uint32_t* pa = &AB[srow[j] * TS + sc4[j] * 4];
            pa[0] = f2tf(av[j].x); pa[1] = f2tf(av[j].y);
            pa[2] = f2tf(av[j].z); pa[3] = f2tf(av[j].w);
            const int dc = sc4[j] * 4;
            const float iv = inv[j];
            VB[(dc + 0) * VS + srow[j]] = f2tf(vv[j].x * iv);
            VB[(dc + 1) * VS + srow[j]] = f2tf(vv[j].y * iv);
            VB[(dc + 2) * VS + srow[j]] = f2tf(vv[j].z * iv);
            VB[(dc + 3) * VS + srow[j]] = f2tf(vv[j].w * iv);
        }
        __syncthreads();

        if (c < 7) {
            const int k0 = (c + 1) * 32;
            #pragma unroll
            for (int j = 0; j < 2; j++) {
                av[j] = *(const float4*)&A[(q0 + srow[j]) * LK + k0 + sc4[j] * 4];
                vv[j] = *(const float4*)&V[(k0 + srow[j]) * DV + d0 + sc4[j] * 4];
                inv[j] = __fdividef(1.0f, CS[k0 + srow[j]]);
            }
        }

        #pragma unroll
        for (int ks = 0; ks < 4; ks++) {
            const int kk = ks * 8;
            uint32_t a[4], bfr[2][2];
            const int r = wq + gid;
            a[0] = AB[r * TS + kk + tig];
            a[1] = AB[(r + 8) * TS + kk + tig];
            a[2] = AB[r * TS + kk + tig + 4];
            a[3] = AB[(r + 8) * TS + kk + tig + 4];
            #pragma unroll
            for (int jn = 0; jn < 2; jn++) {
                int n = wn + jn * 8 + gid;
                bfr[jn][0] = VB[n * VS + kk + tig];
                bfr[jn][1] = VB[n * VS + kk + tig + 4];
            }
            mma8(d[0], a, bfr[0]);
            mma8(d[1], a, bfr[1]);
        }
    }

    float* O = out + b * LQ * DV;
    #pragma unroll
    for (int jn = 0; jn < 2; jn++) {
        int row = q0 + wq + gid;
        int col = d0 + wn + jn * 8 + tig * 2;
        *(float2*)&O[row * DV + col] = make_float2(d[jn][0], d[jn][1]);
        *(float2*)&O[(row + 8) * DV + col] = make_float2(d[jn][2], d[jn][3]);
    }
}

extern "C" void kernel_launch(void* const* d_in, const int* in_sizes, int n_in,
                              void* d_out, int out_size) {
    const float* queries    = (const float*)d_in[0];
    const float* keyes      = (const float*)d_in[1];
    const float* values     = (const float*)d_in[2];
    const int*   valid_lens = (const int*)d_in[3];
    const float* W_q        = (const float*)d_in[4];
    const float* W_k        = (const float*)d_in[5];
    const float* W_v        = (const float*)d_in[6];
    float* out = (float*)d_out;

    proj_kernel<<<dim3(4, 32, 3), 128>>>(queries, W_q, keyes, W_k);
    scores_kernel<<<dim3(8, 16, 8), 256>>>(W_v, valid_lens);
    out_kernel<<<dim3(8, 8, 8), 128>>>(values, out);
}